// round 1
// baseline (speedup 1.0000x reference)
#include <cuda_runtime.h>
#include <cuda_bf16.h>
#include <cstdint>
#include <math.h>

// ---------------------------------------------------------------------------
// Problem constants (fixed instance: B=2048 windows, N_actual=60, C=512)
// ---------------------------------------------------------------------------
#define NWIN_TOK 64          // padded window tokens
#define N_ACT    60          // real tokens per window
#define CDIM     512
#define NHEAD    16
#define HD       32
#define BWIN_MAX 2048
#define SCALE_Q  0.1767766952966369f   // 32^-0.5

// ---------------------------------------------------------------------------
// Device scratch (static __device__ arrays: allocation-guard safe)
// ---------------------------------------------------------------------------
__device__ float g_qkvT[3 * CDIM * CDIM];               // [1536][512]  W^T, tf32-rounded
__device__ float g_projT[CDIM * CDIM];                  // [512][512]   W^T, tf32-rounded
__device__ float g_attn[(size_t)BWIN_MAX * NWIN_TOK * CDIM]; // [B*64][512] attention out (fp32)

// ---------------------------------------------------------------------------
// Helpers
// ---------------------------------------------------------------------------
__device__ __forceinline__ float tf32r(float x) {
    float y;
    asm("cvt.rna.tf32.f32 %0, %1;" : "=f"(y) : "f"(x));
    return y;
}

__device__ __forceinline__ void mma_tf32(float c[4],
                                         uint32_t a0, uint32_t a1, uint32_t a2, uint32_t a3,
                                         uint32_t b0, uint32_t b1) {
    asm volatile(
        "mma.sync.aligned.m16n8k8.row.col.f32.tf32.tf32.f32 "
        "{%0,%1,%2,%3}, {%4,%5,%6,%7}, {%8,%9}, {%0,%1,%2,%3};\n"
        : "+f"(c[0]), "+f"(c[1]), "+f"(c[2]), "+f"(c[3])
        : "r"(a0), "r"(a1), "r"(a2), "r"(a3), "r"(b0), "r"(b1));
}

__device__ __forceinline__ uint32_t f2u(float x) { return __float_as_uint(x); }

// ---------------------------------------------------------------------------
// Kernel 0: transpose + tf32-round a weight matrix.
// which==0: qkv_w [512][1536] -> g_qkvT[1536][512]
// which==1: proj_w [512][512] -> g_projT[512][512]
// Grid: (cols/32, rows/32), block (32,32). Dims are multiples of 32.
// ---------------------------------------------------------------------------
__global__ void ktranspose(const float* __restrict__ src, int R, int Ccols, int which) {
    __shared__ float tile[32][33];
    float* dst = which ? g_projT : g_qkvT;
    int cb = blockIdx.x * 32, rb = blockIdx.y * 32;
    tile[threadIdx.y][threadIdx.x] = src[(size_t)(rb + threadIdx.y) * Ccols + cb + threadIdx.x];
    __syncthreads();
    // dst[n][c] = src[c][n] ; n = cb+ty, c = rb+tx
    dst[(size_t)(cb + threadIdx.y) * R + rb + threadIdx.x] = tf32r(tile[threadIdx.x][threadIdx.y]);
}

// ---------------------------------------------------------------------------
// Kernel 1: fused QKV projection + windowed attention (one CTA per window).
// 512 threads (16 warps). Dynamic smem layout (floats):
//   sx  [64][516]  : padded input window (tf32-rounded)        33024
//   sB  [96][132]  : weight K-chunk (q|k|v rows for one head)  12672
//   sq  [64][36]   : q (scaled, tf32)                           2304
//   sk  [64][36]   : k (tf32)                                   2304
//   svT [32][68]   : v transposed [d][token] (tf32)             2176
//   sS  [64][68]   : scores / probs                             4352
// total 56832 floats = 227328 bytes
// ---------------------------------------------------------------------------
#define SX_STRIDE 516
#define SB_STRIDE 132
#define SQ_STRIDE 36
#define SVT_STRIDE 68
#define SS_STRIDE 68

#define SX_OFF   0
#define SB_OFF   (SX_OFF + 64 * SX_STRIDE)
#define SQ_OFF   (SB_OFF + 96 * SB_STRIDE)
#define SK_OFF   (SQ_OFF + 64 * SQ_STRIDE)
#define SVT_OFF  (SK_OFF + 64 * SQ_STRIDE)
#define SS_OFF   (SVT_OFF + 32 * SVT_STRIDE)
#define K1_SMEM_FLOATS (SS_OFF + 64 * SS_STRIDE)

__global__ __launch_bounds__(512) void k1_qkv_attn(const float* __restrict__ x,
                                                   const float* __restrict__ qkvb) {
    extern __shared__ float sm[];
    float* sx  = sm + SX_OFF;
    float* sB  = sm + SB_OFF;
    float* sq  = sm + SQ_OFF;
    float* sk  = sm + SK_OFF;
    float* svT = sm + SVT_OFF;
    float* sS  = sm + SS_OFF;

    const int b    = blockIdx.x;
    const int tid  = threadIdx.x;
    const int lane = tid & 31;
    const int warp = tid >> 5;
    const int g    = lane >> 2;   // group id 0..7
    const int t    = lane & 3;    // thread-in-group 0..3

    // ---- load window input (rows >= N_ACT are zero) ----
    for (int i = tid; i < 64 * 128; i += 512) {
        int r = i >> 7, c4 = i & 127;
        float4 v;
        if (r < N_ACT) {
            v = *reinterpret_cast<const float4*>(x + ((size_t)b * N_ACT + r) * CDIM + c4 * 4);
            v.x = tf32r(v.x); v.y = tf32r(v.y); v.z = tf32r(v.z); v.w = tf32r(v.w);
        } else {
            v = make_float4(0.f, 0.f, 0.f, 0.f);
        }
        *reinterpret_cast<float4*>(sx + r * SX_STRIDE + c4 * 4) = v;
    }
    __syncthreads();

    for (int head = 0; head < NHEAD; head++) {
        // =============== QKV GEMM for this head: [64 x 96], K = 512 ===========
        // 48 warp tiles (4 m-tiles x 12 n-tiles); warp -> (mt = w&3, 3 n-tiles)
        {
            float acc[3][4];
            #pragma unroll
            for (int j = 0; j < 3; j++)
                #pragma unroll
                for (int q = 0; q < 4; q++) acc[j][q] = 0.f;

            const int mt = warp & 3;
            const int ng = warp >> 2;     // 0..3 -> n-tiles ng*3 + {0,1,2}

            for (int kc = 0; kc < 4; kc++) {           // K chunks of 128
                // load weight chunk: 96 rows (q|k|v of this head) x 128 cols
                for (int i = tid; i < 96 * 32; i += 512) {
                    int row96 = i >> 5, c4 = i & 31;
                    int seg = row96 >> 5, nl = row96 & 31;
                    const float4 v = *reinterpret_cast<const float4*>(
                        g_qkvT + ((size_t)(seg * CDIM + head * HD + nl)) * CDIM + kc * 128 + c4 * 4);
                    *reinterpret_cast<float4*>(sB + row96 * SB_STRIDE + c4 * 4) = v;
                }
                __syncthreads();

                const float* axp = sx + (mt * 16 + g) * SX_STRIDE + kc * 128;
                #pragma unroll 4
                for (int ks = 0; ks < 16; ks++) {
                    const int k0 = ks * 8;
                    uint32_t a0 = f2u(axp[k0 + t]);
                    uint32_t a1 = f2u(axp[8 * SX_STRIDE + k0 + t]);
                    uint32_t a2 = f2u(axp[k0 + t + 4]);
                    uint32_t a3 = f2u(axp[8 * SX_STRIDE + k0 + t + 4]);
                    #pragma unroll
                    for (int j = 0; j < 3; j++) {
                        const int nb = (ng * 3 + j) * 8;
                        uint32_t b0 = f2u(sB[(nb + g) * SB_STRIDE + k0 + t]);
                        uint32_t b1 = f2u(sB[(nb + g) * SB_STRIDE + k0 + t + 4]);
                        mma_tf32(acc[j], a0, a1, a2, a3, b0, b1);
                    }
                }
                __syncthreads();
            }

            // epilogue: bias, q-scale, scatter to sq / sk / svT (tf32-rounded)
            #pragma unroll
            for (int j = 0; j < 3; j++) {
                const int nb = (ng * 3 + j) * 8;
                #pragma unroll
                for (int q = 0; q < 4; q++) {
                    int row   = mt * 16 + g + ((q >= 2) ? 8 : 0);
                    int col96 = nb + 2 * t + (q & 1);
                    int seg = col96 >> 5, d = col96 & 31;
                    float v = acc[j][q] + qkvb[seg * CDIM + head * HD + d];
                    if (seg == 0)      sq[row * SQ_STRIDE + d]  = tf32r(v * SCALE_Q);
                    else if (seg == 1) sk[row * SQ_STRIDE + d]  = tf32r(v);
                    else               svT[d * SVT_STRIDE + row] = tf32r(v);
                }
            }
        }
        __syncthreads();

        // =============== scores S = q @ k^T : [64 x 64], K = 32 ===============
        {
            float sacc[2][4];
            #pragma unroll
            for (int j = 0; j < 2; j++)
                #pragma unroll
                for (int q = 0; q < 4; q++) sacc[j][q] = 0.f;

            const int mt  = warp & 3;
            const int nt2 = warp >> 2;   // n-tiles nt2*2 + {0,1}
            #pragma unroll
            for (int ks = 0; ks < 4; ks++) {
                const int k0 = ks * 8;
                const float* aq = sq + (mt * 16 + g) * SQ_STRIDE;
                uint32_t a0 = f2u(aq[k0 + t]);
                uint32_t a1 = f2u(aq[8 * SQ_STRIDE + k0 + t]);
                uint32_t a2 = f2u(aq[k0 + t + 4]);
                uint32_t a3 = f2u(aq[8 * SQ_STRIDE + k0 + t + 4]);
                #pragma unroll
                for (int j = 0; j < 2; j++) {
                    const int nb = (nt2 * 2 + j) * 8;
                    uint32_t b0 = f2u(sk[(nb + g) * SQ_STRIDE + k0 + t]);
                    uint32_t b1 = f2u(sk[(nb + g) * SQ_STRIDE + k0 + t + 4]);
                    mma_tf32(sacc[j], a0, a1, a2, a3, b0, b1);
                }
            }
            // write scores with additive key-padding mask (cols >= N_ACT)
            #pragma unroll
            for (int j = 0; j < 2; j++) {
                const int nb = (nt2 * 2 + j) * 8;
                #pragma unroll
                for (int q = 0; q < 4; q++) {
                    int row = (warp & 3) * 16 + g + ((q >= 2) ? 8 : 0);
                    int col = nb + 2 * t + (q & 1);
                    float v = sacc[j][q];
                    if (col >= N_ACT) v += -1e9f;
                    sS[row * SS_STRIDE + col] = v;
                }
            }
        }
        __syncthreads();

        // =============== softmax rows (8 threads per row) =====================
        {
            const int r  = tid >> 3;
            const int s8 = tid & 7;
            float* row = sS + r * SS_STRIDE + s8 * 8;
            float v[8];
            float m = -1e30f;
            #pragma unroll
            for (int i = 0; i < 8; i++) { v[i] = row[i]; m = fmaxf(m, v[i]); }
            #pragma unroll
            for (int o = 1; o < 8; o <<= 1) m = fmaxf(m, __shfl_xor_sync(0xffffffffu, m, o));
            float s = 0.f;
            #pragma unroll
            for (int i = 0; i < 8; i++) { v[i] = __expf(v[i] - m); s += v[i]; }
            #pragma unroll
            for (int o = 1; o < 8; o <<= 1) s += __shfl_xor_sync(0xffffffffu, s, o);
            const float inv = 1.f / s;
            #pragma unroll
            for (int i = 0; i < 8; i++) row[i] = tf32r(v[i] * inv);
        }
        __syncthreads();

        // =============== O = P @ V : [64 x 32], K = 64 ========================
        {
            float oacc[4] = {0.f, 0.f, 0.f, 0.f};
            const int mt = warp & 3;
            const int nt = warp >> 2;   // 4 n-tiles -> 32 cols
            #pragma unroll
            for (int ks = 0; ks < 8; ks++) {
                const int k0 = ks * 8;
                const float* ap = sS + (mt * 16 + g) * SS_STRIDE;
                uint32_t a0 = f2u(ap[k0 + t]);
                uint32_t a1 = f2u(ap[8 * SS_STRIDE + k0 + t]);
                uint32_t a2 = f2u(ap[k0 + t + 4]);
                uint32_t a3 = f2u(ap[8 * SS_STRIDE + k0 + t + 4]);
                uint32_t b0 = f2u(svT[(nt * 8 + g) * SVT_STRIDE + k0 + t]);
                uint32_t b1 = f2u(svT[(nt * 8 + g) * SVT_STRIDE + k0 + t + 4]);
                mma_tf32(oacc, a0, a1, a2, a3, b0, b1);
            }
            #pragma unroll
            for (int q = 0; q < 4; q++) {
                int row = mt * 16 + g + ((q >= 2) ? 8 : 0);
                int col = head * HD + nt * 8 + 2 * t + (q & 1);
                g_attn[((size_t)b * NWIN_TOK + row) * CDIM + col] = oacc[q];
            }
        }
        __syncthreads();
    }
}

// ---------------------------------------------------------------------------
// Kernel 2: proj GEMM  out[b, r<60, :] = g_attn[b*64 + r, :] @ proj_w + pb
// CTA tile 128x128, 512 threads. K chunks of 64. smem 2*128*68 floats.
// ---------------------------------------------------------------------------
#define K2_TSTRIDE 68
#define K2_SMEM_FLOATS (2 * 128 * K2_TSTRIDE)

__global__ __launch_bounds__(512) void k2_proj(const float* __restrict__ pb,
                                               float* __restrict__ out) {
    extern __shared__ float sm[];
    float* sA  = sm;
    float* sBp = sm + 128 * K2_TSTRIDE;

    const int bid = blockIdx.x;
    const int n0  = (bid & 3) * 128;
    const int m0  = (bid >> 2) * 128;
    const int tid = threadIdx.x;
    const int lane = tid & 31;
    const int warp = tid >> 5;
    const int g = lane >> 2, t = lane & 3;
    const int wm = warp & 3;      // m-subtiles {wm*2, wm*2+1}
    const int wn = warp >> 2;     // n-subtiles {wn*4 .. wn*4+3}

    float acc[2][4][4];
    #pragma unroll
    for (int im = 0; im < 2; im++)
        #pragma unroll
        for (int in_ = 0; in_ < 4; in_++)
            #pragma unroll
            for (int q = 0; q < 4; q++) acc[im][in_][q] = 0.f;

    for (int kc = 0; kc < 8; kc++) {
        for (int i = tid; i < 2048; i += 512) {
            int r = i >> 4, c4 = i & 15;
            float4 v = *reinterpret_cast<const float4*>(
                g_attn + ((size_t)(m0 + r)) * CDIM + kc * 64 + c4 * 4);
            v.x = tf32r(v.x); v.y = tf32r(v.y); v.z = tf32r(v.z); v.w = tf32r(v.w);
            *reinterpret_cast<float4*>(sA + r * K2_TSTRIDE + c4 * 4) = v;
        }
        for (int i = tid; i < 2048; i += 512) {
            int r = i >> 4, c4 = i & 15;
            float4 v = *reinterpret_cast<const float4*>(
                g_projT + ((size_t)(n0 + r)) * CDIM + kc * 64 + c4 * 4);
            *reinterpret_cast<float4*>(sBp + r * K2_TSTRIDE + c4 * 4) = v;
        }
        __syncthreads();

        #pragma unroll 2
        for (int ks = 0; ks < 8; ks++) {
            const int k0 = ks * 8;
            uint32_t a[2][4];
            #pragma unroll
            for (int im = 0; im < 2; im++) {
                const float* ap = sA + ((wm * 2 + im) * 16 + g) * K2_TSTRIDE;
                a[im][0] = f2u(ap[k0 + t]);
                a[im][1] = f2u(ap[8 * K2_TSTRIDE + k0 + t]);
                a[im][2] = f2u(ap[k0 + t + 4]);
                a[im][3] = f2u(ap[8 * K2_TSTRIDE + k0 + t + 4]);
            }
            uint32_t bb[4][2];
            #pragma unroll
            for (int in_ = 0; in_ < 4; in_++) {
                const int nb = (wn * 4 + in_) * 8;
                bb[in_][0] = f2u(sBp[(nb + g) * K2_TSTRIDE + k0 + t]);
                bb[in_][1] = f2u(sBp[(nb + g) * K2_TSTRIDE + k0 + t + 4]);
            }
            #pragma unroll
            for (int im = 0; im < 2; im++)
                #pragma unroll
                for (int in_ = 0; in_ < 4; in_++)
                    mma_tf32(acc[im][in_], a[im][0], a[im][1], a[im][2], a[im][3],
                             bb[in_][0], bb[in_][1]);
        }
        __syncthreads();
    }

    // epilogue: bias + trim rows (window-local row >= 60 dropped)
    #pragma unroll
    for (int im = 0; im < 2; im++) {
        #pragma unroll
        for (int in_ = 0; in_ < 4; in_++) {
            const int nbase = n0 + (wn * 4 + in_) * 8;
            #pragma unroll
            for (int q = 0; q < 4; q++) {
                int row = m0 + (wm * 2 + im) * 16 + g + ((q >= 2) ? 8 : 0);
                int col = nbase + 2 * t + (q & 1);
                float v = acc[im][in_][q] + pb[col];
                int bw = row >> 6, r64 = row & 63;
                if (r64 < N_ACT)
                    out[((size_t)bw * N_ACT + r64) * CDIM + col] = v;
            }
        }
    }
}

// ---------------------------------------------------------------------------
// Launch
// ---------------------------------------------------------------------------
extern "C" void kernel_launch(void* const* d_in, const int* in_sizes, int n_in,
                              void* d_out, int out_size) {
    // defensive input mapping by element count
    const float *x = nullptr, *qkvw = nullptr, *qkvb = nullptr, *projw = nullptr, *projb = nullptr;
    int x_elems = 0;
    for (int i = 0; i < n_in; i++) {
        int s = in_sizes[i];
        if (s == CDIM * 3 * CDIM)      qkvw = (const float*)d_in[i];
        else if (s == 3 * CDIM)        qkvb = (const float*)d_in[i];
        else if (s == CDIM * CDIM)     projw = (const float*)d_in[i];
        else if (s == CDIM)            projb = (const float*)d_in[i];
        else { x = (const float*)d_in[i]; x_elems = s; }
    }
    float* out = (float*)d_out;
    const int B = x_elems / (N_ACT * CDIM);   // 2048

    // opt-in to large dynamic smem (idempotent; harmless error ignored if
    // called during graph capture — first call happens in the correctness run)
    static bool attr_done = false;
    (void)attr_done;
    cudaFuncSetAttribute(k1_qkv_attn, cudaFuncAttributeMaxDynamicSharedMemorySize,
                         K1_SMEM_FLOATS * (int)sizeof(float));
    cudaFuncSetAttribute(k2_proj, cudaFuncAttributeMaxDynamicSharedMemorySize,
                         K2_SMEM_FLOATS * (int)sizeof(float));

    // weight pre-transpose + tf32 rounding
    ktranspose<<<dim3(3 * CDIM / 32, CDIM / 32), dim3(32, 32)>>>(qkvw, CDIM, 3 * CDIM, 0);
    ktranspose<<<dim3(CDIM / 32, CDIM / 32), dim3(32, 32)>>>(projw, CDIM, CDIM, 1);

    // fused QKV + attention (one CTA per window)
    k1_qkv_attn<<<B, 512, K1_SMEM_FLOATS * sizeof(float)>>>(x, qkvb);

    // projection GEMM + trim
    const int grid2 = (B * NWIN_TOK / 128) * (CDIM / 128);
    k2_proj<<<grid2, 512, K2_SMEM_FLOATS * sizeof(float)>>>(projb, out);
}

// round 6
// speedup vs baseline: 1.5574x; 1.5574x over previous
#include <cuda_runtime.h>
#include <cuda_bf16.h>
#include <cstdint>

// ---------------------------------------------------------------------------
// Problem constants (fixed instance: B=2048 windows, N_actual=60, C=512)
// ---------------------------------------------------------------------------
#define N_ACT    60
#define CDIM     512
#define NHEAD    16
#define HD       32
#define BWIN     2048
#define MROWS    (BWIN * N_ACT)          // 122880 = 960 * 128
#define SCALE_Q  0.1767766952966369f     // 32^-0.5

// ---------------------------------------------------------------------------
// Device scratch (static __device__ arrays: allocation-guard safe)
// g_qkv: [122880][1536] = q|k|v (tf32, biased, q scaled). After k_attn, the
// q columns [0,512) are overwritten with the attention output (fp32).
// ---------------------------------------------------------------------------
__device__ float g_qkvT[3 * CDIM * CDIM];            // [1536][512] W^T tf32-rounded
__device__ float g_projT[CDIM * CDIM];               // [512][512]  W^T tf32-rounded
__device__ float g_qkv[(size_t)MROWS * 3 * CDIM];    // [122880][1536]

// ---------------------------------------------------------------------------
// Helpers
// ---------------------------------------------------------------------------
__device__ __forceinline__ float tf32r(float x) {
    float y;
    asm("cvt.rna.tf32.f32 %0, %1;" : "=f"(y) : "f"(x));
    return y;
}
__device__ __forceinline__ uint32_t f2u(float x) { return __float_as_uint(x); }

__device__ __forceinline__ void mma_tf32(float c[4],
                                         float a0, float a1, float a2, float a3,
                                         float b0, float b1) {
    asm volatile(
        "mma.sync.aligned.m16n8k8.row.col.f32.tf32.tf32.f32 "
        "{%0,%1,%2,%3}, {%4,%5,%6,%7}, {%8,%9}, {%0,%1,%2,%3};\n"
        : "+f"(c[0]), "+f"(c[1]), "+f"(c[2]), "+f"(c[3])
        : "r"(f2u(a0)), "r"(f2u(a1)), "r"(f2u(a2)), "r"(f2u(a3)),
          "r"(f2u(b0)), "r"(f2u(b1)));
}

// ---------------------------------------------------------------------------
// Kernel 0: transpose + tf32-round weights.
// which==0: qkv_w [512][1536] -> g_qkvT[1536][512]
// which==1: proj_w [512][512] -> g_projT[512][512]
// ---------------------------------------------------------------------------
__global__ void ktranspose(const float* __restrict__ src, int R, int Ccols, int which) {
    __shared__ float tile[32][33];
    float* dst = which ? g_projT : g_qkvT;
    int cb = blockIdx.x * 32, rb = blockIdx.y * 32;
    tile[threadIdx.y][threadIdx.x] = src[(size_t)(rb + threadIdx.y) * Ccols + cb + threadIdx.x];
    __syncthreads();
    dst[(size_t)(cb + threadIdx.y) * R + rb + threadIdx.x] = tf32r(tile[threadIdx.x][threadIdx.y]);
}

// ---------------------------------------------------------------------------
// Tiled tf32 GEMM, CTA tile 128x128, 256 threads (8 warps = 4m x 2n),
// warp tile 32x64. K-chunk 32. Static smem 2 x 128 x 40 floats = 40960 B.
//
// smem layout per 32-wide chunk row: 4 groups of 8 logical cols, group
// stride 10 floats, element (r,c) -> r*40 + (c>>3)*10 + 2*(c&3) + ((c>>2)&1).
// Fragment pair (k=8m+t, 8m+t+4) is one aligned float2 at (m*10 + 2t).
// Loads (LDS.64) and stores (STS.64) are bank-conflict-free.
//
// mode 0: A=x (lda 512),   B=g_qkvT,  bias=qkvb,  C=g_qkv (ldc 1536),
//         q-columns (<512) scaled, output tf32-rounded.
// mode 1: A=g_qkv (lda 1536, attention out in cols 0..511), B=g_projT,
//         bias=projb, C=out (ldc 512).
// ---------------------------------------------------------------------------
#define GST 40

__global__ __launch_bounds__(256, 2) void kgemm(const float* __restrict__ xin,
                                                const float* __restrict__ qkvb,
                                                const float* __restrict__ projb,
                                                float* __restrict__ out,
                                                int mode) {
    __shared__ float sA[128 * GST];
    __shared__ float sB[128 * GST];

    const float* Aptr = mode ? g_qkv : xin;
    const int    lda  = mode ? (3 * CDIM) : CDIM;
    const float* Bw   = mode ? g_projT : g_qkvT;
    const float* bias = mode ? projb : qkvb;
    float*       Cp   = mode ? out : g_qkv;
    const int    ldc  = mode ? CDIM : (3 * CDIM);

    const int m0 = blockIdx.y * 128;
    const int n0 = blockIdx.x * 128;
    const int tid  = threadIdx.x;
    const int lane = tid & 31;
    const int warp = tid >> 5;
    const int g = lane >> 2, t = lane & 3;
    const int wm = warp & 3;       // 4 m-stripes of 32 rows
    const int wn = warp >> 2;      // 2 n-stripes of 64 cols
    const int lr   = tid >> 2;     // load row 0..63 (+64 second half)
    const int lgrp = tid & 3;      // load group 0..3

    float acc[2][8][4];
    #pragma unroll
    for (int im = 0; im < 2; im++)
        #pragma unroll
        for (int jn = 0; jn < 8; jn++)
            #pragma unroll
            for (int q = 0; q < 4; q++) acc[im][jn][q] = 0.f;

    const float* aBase = sA + (wm * 32 + g) * GST + 2 * t;
    const float* bBase = sB + (wn * 64 + g) * GST + 2 * t;

    for (int kc = 0; kc < 16; kc++) {
        // ---- stage A chunk [128 x 32] (tf32-round) ----
        #pragma unroll
        for (int h = 0; h < 2; h++) {
            const int r = lr + h * 64;
            const float* p = Aptr + (size_t)(m0 + r) * lda + kc * 32 + lgrp * 8;
            float4 v0 = *reinterpret_cast<const float4*>(p);
            float4 v1 = *reinterpret_cast<const float4*>(p + 4);
            float* s = sA + r * GST + lgrp * 10;
            *reinterpret_cast<float2*>(s + 0) = make_float2(tf32r(v0.x), tf32r(v1.x));
            *reinterpret_cast<float2*>(s + 2) = make_float2(tf32r(v0.y), tf32r(v1.y));
            *reinterpret_cast<float2*>(s + 4) = make_float2(tf32r(v0.z), tf32r(v1.z));
            *reinterpret_cast<float2*>(s + 6) = make_float2(tf32r(v0.w), tf32r(v1.w));
        }
        // ---- stage B chunk [128 x 32] (already tf32) ----
        #pragma unroll
        for (int h = 0; h < 2; h++) {
            const int r = lr + h * 64;
            const float* p = Bw + (size_t)(n0 + r) * CDIM + kc * 32 + lgrp * 8;
            float4 v0 = *reinterpret_cast<const float4*>(p);
            float4 v1 = *reinterpret_cast<const float4*>(p + 4);
            float* s = sB + r * GST + lgrp * 10;
            *reinterpret_cast<float2*>(s + 0) = make_float2(v0.x, v1.x);
            *reinterpret_cast<float2*>(s + 2) = make_float2(v0.y, v1.y);
            *reinterpret_cast<float2*>(s + 4) = make_float2(v0.z, v1.z);
            *reinterpret_cast<float2*>(s + 6) = make_float2(v0.w, v1.w);
        }
        __syncthreads();

        #pragma unroll
        for (int ks = 0; ks < 4; ks++) {
            const int kb = ks * 10;
            float2 a00 = *reinterpret_cast<const float2*>(aBase + kb);
            float2 a01 = *reinterpret_cast<const float2*>(aBase + 8 * GST + kb);
            float2 a10 = *reinterpret_cast<const float2*>(aBase + 16 * GST + kb);
            float2 a11 = *reinterpret_cast<const float2*>(aBase + 24 * GST + kb);
            float2 bv[8];
            #pragma unroll
            for (int jn = 0; jn < 8; jn++)
                bv[jn] = *reinterpret_cast<const float2*>(bBase + jn * 8 * GST + kb);
            #pragma unroll
            for (int jn = 0; jn < 8; jn++) {
                mma_tf32(acc[0][jn], a00.x, a01.x, a00.y, a01.y, bv[jn].x, bv[jn].y);
                mma_tf32(acc[1][jn], a10.x, a11.x, a10.y, a11.y, bv[jn].x, bv[jn].y);
            }
        }
        __syncthreads();
    }

    // ---- epilogue: bias (+ q-scale / tf32 round for mode 0) ----
    #pragma unroll
    for (int im = 0; im < 2; im++) {
        #pragma unroll
        for (int jn = 0; jn < 8; jn++) {
            #pragma unroll
            for (int q = 0; q < 4; q++) {
                const int row = m0 + wm * 32 + im * 16 + g + ((q >= 2) ? 8 : 0);
                const int col = n0 + wn * 64 + jn * 8 + 2 * t + (q & 1);
                float v = acc[im][jn][q] + bias[col];
                if (mode == 0) {
                    if (col < CDIM) v *= SCALE_Q;
                    Cp[(size_t)row * ldc + col] = tf32r(v);
                } else {
                    Cp[(size_t)row * ldc + col] = v;
                }
            }
        }
    }
}

// ---------------------------------------------------------------------------
// Attention kernel: one CTA per (window, head). 128 threads (4 warps).
// Loads q,k,v (60x32 each) from g_qkv into permuted smem, S = q@k^T (64x64),
// register softmax with key-padding mask, O = P@V, writes O (60x32) back into
// the q-slot of g_qkv (q is dead after the smem load + barrier).
// Static smem 48128 B.
// ---------------------------------------------------------------------------
__global__ __launch_bounds__(128) void k_attn() {
    __shared__ float sq[64 * 40];
    __shared__ float sk[64 * 40];
    __shared__ float svT[32 * 72];
    __shared__ float sS[64 * 72];

    const int b = blockIdx.x;
    const int h = blockIdx.y;
    const int tid  = threadIdx.x;
    const int lane = tid & 31;
    const int warp = tid >> 5;
    const int g = lane >> 2, t = lane & 3;

    const float* qb = g_qkv + (size_t)b * N_ACT * (3 * CDIM) + h * HD;
    const float* kb = qb + CDIM;
    const float* vb = qb + 2 * CDIM;

    // ---- load q, k (perm-8 layout, stride 40), v transposed (stride 72) ----
    for (int i = tid; i < 64 * 8; i += 128) {
        int r = i >> 3, c4 = i & 7, cb = c4 * 4;
        float4 vq, vk, vv;
        if (r < N_ACT) {
            vq = *reinterpret_cast<const float4*>(qb + (size_t)r * (3 * CDIM) + cb);
            vk = *reinterpret_cast<const float4*>(kb + (size_t)r * (3 * CDIM) + cb);
            vv = *reinterpret_cast<const float4*>(vb + (size_t)r * (3 * CDIM) + cb);
        } else {
            vq = vk = vv = make_float4(0.f, 0.f, 0.f, 0.f);
        }
        int base = r * 40 + (cb & 24) + ((cb >> 2) & 1);
        sq[base + 0] = vq.x; sq[base + 2] = vq.y; sq[base + 4] = vq.z; sq[base + 6] = vq.w;
        sk[base + 0] = vk.x; sk[base + 2] = vk.y; sk[base + 4] = vk.z; sk[base + 6] = vk.w;
        int pr = (r & 56) + (r & 3) * 2 + ((r >> 2) & 1);   // permuted token pos
        svT[(cb + 0) * 72 + pr] = vv.x;
        svT[(cb + 1) * 72 + pr] = vv.y;
        svT[(cb + 2) * 72 + pr] = vv.z;
        svT[(cb + 3) * 72 + pr] = vv.w;
    }
    __syncthreads();

    // ---- scores S = q @ k^T : warp handles rows 16*warp..+15 ----
    float sacc[8][4];
    #pragma unroll
    for (int jn = 0; jn < 8; jn++)
        #pragma unroll
        for (int q = 0; q < 4; q++) sacc[jn][q] = 0.f;

    #pragma unroll
    for (int ks = 0; ks < 4; ks++) {
        const int k0 = ks * 8 + 2 * t;
        const float* ap = sq + (16 * warp + g) * 40 + k0;
        float2 a0 = *reinterpret_cast<const float2*>(ap);
        float2 a1 = *reinterpret_cast<const float2*>(ap + 8 * 40);
        #pragma unroll
        for (int jn = 0; jn < 8; jn++) {
            float2 bp = *reinterpret_cast<const float2*>(sk + (jn * 8 + g) * 40 + k0);
            mma_tf32(sacc[jn], a0.x, a1.x, a0.y, a1.y, bp.x, bp.y);
        }
    }

    // ---- mask + register softmax (rows r0=16w+g, r1=r0+8) ----
    float mx[2] = {-1e30f, -1e30f};
    #pragma unroll
    for (int jn = 0; jn < 8; jn++)
        #pragma unroll
        for (int q = 0; q < 4; q++) {
            int col = jn * 8 + 2 * t + (q & 1);
            float v = sacc[jn][q] + (col >= N_ACT ? -1e9f : 0.f);
            sacc[jn][q] = v;
            mx[q >> 1] = fmaxf(mx[q >> 1], v);
        }
    #pragma unroll
    for (int o = 1; o < 4; o <<= 1) {
        mx[0] = fmaxf(mx[0], __shfl_xor_sync(0xffffffffu, mx[0], o));
        mx[1] = fmaxf(mx[1], __shfl_xor_sync(0xffffffffu, mx[1], o));
    }
    float sum[2] = {0.f, 0.f};
    #pragma unroll
    for (int jn = 0; jn < 8; jn++)
        #pragma unroll
        for (int q = 0; q < 4; q++) {
            float e = __expf(sacc[jn][q] - mx[q >> 1]);
            sacc[jn][q] = e;
            sum[q >> 1] += e;
        }
    #pragma unroll
    for (int o = 1; o < 4; o <<= 1) {
        sum[0] += __shfl_xor_sync(0xffffffffu, sum[0], o);
        sum[1] += __shfl_xor_sync(0xffffffffu, sum[1], o);
    }
    const float inv0 = 1.f / sum[0], inv1 = 1.f / sum[1];

    // store P (tf32) into sS with perm-8 k layout (own-warp rows only)
    #pragma unroll
    for (int jn = 0; jn < 8; jn++)
        #pragma unroll
        for (int q = 0; q < 4; q++) {
            int col = jn * 8 + 2 * t + (q & 1);
            int row = 16 * warp + g + ((q >= 2) ? 8 : 0);
            int pc = (col & 56) + (col & 3) * 2 + ((col >> 2) & 1);
            sS[row * 72 + pc] = tf32r(sacc[jn][q] * ((q >= 2) ? inv1 : inv0));
        }
    __syncwarp();

    // ---- O = P @ V : [16 x 32] per warp, K = 64 ----
    float oacc[4][4];
    #pragma unroll
    for (int jn = 0; jn < 4; jn++)
        #pragma unroll
        for (int q = 0; q < 4; q++) oacc[jn][q] = 0.f;

    #pragma unroll
    for (int ks = 0; ks < 8; ks++) {
        const int k0 = ks * 8 + 2 * t;
        const float* ap = sS + (16 * warp + g) * 72 + k0;
        float2 a0 = *reinterpret_cast<const float2*>(ap);
        float2 a1 = *reinterpret_cast<const float2*>(ap + 8 * 72);
        #pragma unroll
        for (int jn = 0; jn < 4; jn++) {
            float2 bp = *reinterpret_cast<const float2*>(svT + (jn * 8 + g) * 72 + k0);
            mma_tf32(oacc[jn], a0.x, a1.x, a0.y, a1.y, bp.x, bp.y);
        }
    }

    // ---- write O into q-slot of g_qkv (dead after load barrier) ----
    #pragma unroll
    for (int jn = 0; jn < 4; jn++)
        #pragma unroll
        for (int q = 0; q < 4; q++) {
            int row = 16 * warp + g + ((q >= 2) ? 8 : 0);
            int col = jn * 8 + 2 * t + (q & 1);
            if (row < N_ACT)
                g_qkv[((size_t)b * N_ACT + row) * (3 * CDIM) + h * HD + col] = oacc[jn][q];
        }
}

// ---------------------------------------------------------------------------
// Launch (no cudaFuncSetAttribute, no dynamic smem, no templates)
// ---------------------------------------------------------------------------
extern "C" void kernel_launch(void* const* d_in, const int* in_sizes, int n_in,
                              void* d_out, int out_size) {
    const float *x = nullptr, *qkvw = nullptr, *qkvb = nullptr, *projw = nullptr, *projb = nullptr;
    for (int i = 0; i < n_in; i++) {
        int s = in_sizes[i];
        if (s == CDIM * 3 * CDIM)      qkvw = (const float*)d_in[i];
        else if (s == 3 * CDIM)        qkvb = (const float*)d_in[i];
        else if (s == CDIM * CDIM)     projw = (const float*)d_in[i];
        else if (s == CDIM)            projb = (const float*)d_in[i];
        else                           x = (const float*)d_in[i];
    }
    float* out = (float*)d_out;

    // weight pre-transpose + tf32 rounding
    ktranspose<<<dim3(3 * CDIM / 32, CDIM / 32), dim3(32, 32)>>>(qkvw, CDIM, 3 * CDIM, 0);
    ktranspose<<<dim3(CDIM / 32, CDIM / 32), dim3(32, 32)>>>(projw, CDIM, CDIM, 1);

    // QKV GEMM: g_qkv[122880 x 1536] = x @ qkv_w (+bias, q*scale, tf32 round)
    kgemm<<<dim3(3 * CDIM / 128, MROWS / 128), 256>>>(x, qkvb, projb, out, 0);

    // attention per (window, head); O overwrites q-slot of g_qkv
    k_attn<<<dim3(BWIN, NHEAD), 128>>>();

    // proj GEMM: out[122880 x 512] = O @ proj_w + bias
    kgemm<<<dim3(CDIM / 128, MROWS / 128), 256>>>(x, qkvb, projb, out, 1);
}

// round 10
// speedup vs baseline: 1.6701x; 1.0724x over previous
#include <cuda_runtime.h>
#include <cuda_bf16.h>
#include <cstdint>

// ---------------------------------------------------------------------------
// Problem constants (fixed instance: B=2048 windows, N_actual=60, C=512)
// ---------------------------------------------------------------------------
#define N_ACT    60
#define CDIM     512
#define NHEAD    16
#define HD       32
#define BWIN     2048
#define MROWS    (BWIN * N_ACT)          // 122880 = 960 * 128
#define SCALE_Q  0.1767766952966369f     // 32^-0.5

// ---------------------------------------------------------------------------
// Device scratch (static __device__ arrays: allocation-guard safe)
// ---------------------------------------------------------------------------
__device__ float g_qkvT[3 * CDIM * CDIM];            // [1536][512] W^T tf32-rounded
__device__ float g_projT[CDIM * CDIM];               // [512][512]  W^T tf32-rounded
__device__ float g_qkv[(size_t)MROWS * 3 * CDIM];    // [122880][1536] q|k|v; q-slot -> attn out

// ---------------------------------------------------------------------------
// Helpers
// ---------------------------------------------------------------------------
__device__ __forceinline__ float tf32r(float x) {
    float y;
    asm("cvt.rna.tf32.f32 %0, %1;" : "=f"(y) : "f"(x));
    return y;
}
__device__ __forceinline__ uint32_t f2u(float x) { return __float_as_uint(x); }

__device__ __forceinline__ void mma_tf32(float c[4],
                                         float a0, float a1, float a2, float a3,
                                         float b0, float b1) {
    asm volatile(
        "mma.sync.aligned.m16n8k8.row.col.f32.tf32.tf32.f32 "
        "{%0,%1,%2,%3}, {%4,%5,%6,%7}, {%8,%9}, {%0,%1,%2,%3};\n"
        : "+f"(c[0]), "+f"(c[1]), "+f"(c[2]), "+f"(c[3])
        : "r"(f2u(a0)), "r"(f2u(a1)), "r"(f2u(a2)), "r"(f2u(a3)),
          "r"(f2u(b0)), "r"(f2u(b1)));
}

// ---------------------------------------------------------------------------
// Kernel 0: transpose + tf32-round weights.
// which==0: qkv_w [512][1536] -> g_qkvT[1536][512]
// which==1: proj_w [512][512] -> g_projT[512][512]
// ---------------------------------------------------------------------------
__global__ void ktranspose(const float* __restrict__ src, int R, int Ccols, int which) {
    __shared__ float tile[32][33];
    float* dst = which ? g_projT : g_qkvT;
    int cb = blockIdx.x * 32, rb = blockIdx.y * 32;
    tile[threadIdx.y][threadIdx.x] = src[(size_t)(rb + threadIdx.y) * Ccols + cb + threadIdx.x];
    __syncthreads();
    dst[(size_t)(cb + threadIdx.y) * R + rb + threadIdx.x] = tf32r(tile[threadIdx.x][threadIdx.y]);
}

// ---------------------------------------------------------------------------
// Tiled tf32 GEMM, CTA tile 128x128, 128 threads (4 warps = 2m x 2n),
// warp tile 64x64 (4 m-subtiles x 8 n-subtiles of m16n8k8).
// K-chunk 32. Static smem 2 x 128 x 40 floats = 40960 B.
//
// smem layout per 32-wide chunk row: 4 groups of 8 logical cols, group
// stride 10 floats, element (r,c) -> r*40 + (c>>3)*10 + 2*(c&3) + ((c>>2)&1).
// Fragment pair (k=8m+t, 8m+t+4) is one aligned float2 at (m*10 + 2t).
//
// mode 0: A=x (lda 512),   B=g_qkvT,  bias=qkvb,  C=g_qkv (ldc 1536),
//         q-columns (<512) scaled, output tf32-rounded.
// mode 1: A=g_qkv (lda 1536, attention out in cols 0..511), B=g_projT,
//         bias=projb, C=out (ldc 512).
// ---------------------------------------------------------------------------
#define GST 40

__global__ __launch_bounds__(128, 2) void kgemm(const float* __restrict__ xin,
                                                const float* __restrict__ qkvb,
                                                const float* __restrict__ projb,
                                                float* __restrict__ out,
                                                int mode) {
    __shared__ float sA[128 * GST];
    __shared__ float sB[128 * GST];

    const float* Aptr = mode ? g_qkv : xin;
    const int    lda  = mode ? (3 * CDIM) : CDIM;
    const float* Bw   = mode ? g_projT : g_qkvT;
    const float* bias = mode ? projb : qkvb;
    float*       Cp   = mode ? out : g_qkv;
    const int    ldc  = mode ? CDIM : (3 * CDIM);

    const int m0 = blockIdx.y * 128;
    const int n0 = blockIdx.x * 128;
    const int tid  = threadIdx.x;
    const int lane = tid & 31;
    const int warp = tid >> 5;
    const int g = lane >> 2, t = lane & 3;
    const int wm = warp & 1;       // 2 m-stripes of 64 rows
    const int wn = warp >> 1;      // 2 n-stripes of 64 cols
    const int lr   = tid >> 2;     // load row 0..31 (+32*j)
    const int lgrp = tid & 3;      // load group 0..3

    float acc[4][8][4];
    #pragma unroll
    for (int im = 0; im < 4; im++)
        #pragma unroll
        for (int jn = 0; jn < 8; jn++)
            #pragma unroll
            for (int q = 0; q < 4; q++) acc[im][jn][q] = 0.f;

    const float* aBase = sA + (wm * 64 + g) * GST + 2 * t;
    const float* bBase = sB + (wn * 64 + g) * GST + 2 * t;

    for (int kc = 0; kc < 16; kc++) {
        // ---- stage A chunk [128 x 32] (tf32-round) ----
        #pragma unroll
        for (int j = 0; j < 4; j++) {
            const int r = lr + j * 32;
            const float* p = Aptr + (size_t)(m0 + r) * lda + kc * 32 + lgrp * 8;
            float4 v0 = *reinterpret_cast<const float4*>(p);
            float4 v1 = *reinterpret_cast<const float4*>(p + 4);
            float* s = sA + r * GST + lgrp * 10;
            *reinterpret_cast<float2*>(s + 0) = make_float2(tf32r(v0.x), tf32r(v1.x));
            *reinterpret_cast<float2*>(s + 2) = make_float2(tf32r(v0.y), tf32r(v1.y));
            *reinterpret_cast<float2*>(s + 4) = make_float2(tf32r(v0.z), tf32r(v1.z));
            *reinterpret_cast<float2*>(s + 6) = make_float2(tf32r(v0.w), tf32r(v1.w));
        }
        // ---- stage B chunk [128 x 32] (already tf32) ----
        #pragma unroll
        for (int j = 0; j < 4; j++) {
            const int r = lr + j * 32;
            const float* p = Bw + (size_t)(n0 + r) * CDIM + kc * 32 + lgrp * 8;
            float4 v0 = *reinterpret_cast<const float4*>(p);
            float4 v1 = *reinterpret_cast<const float4*>(p + 4);
            float* s = sB + r * GST + lgrp * 10;
            *reinterpret_cast<float2*>(s + 0) = make_float2(v0.x, v1.x);
            *reinterpret_cast<float2*>(s + 2) = make_float2(v0.y, v1.y);
            *reinterpret_cast<float2*>(s + 4) = make_float2(v0.z, v1.z);
            *reinterpret_cast<float2*>(s + 6) = make_float2(v0.w, v1.w);
        }
        __syncthreads();

        #pragma unroll
        for (int ks = 0; ks < 4; ks++) {
            const int kb = ks * 10;
            float2 av[4][2];
            #pragma unroll
            for (int im = 0; im < 4; im++) {
                const float* ap = aBase + im * 16 * GST + kb;
                av[im][0] = *reinterpret_cast<const float2*>(ap);
                av[im][1] = *reinterpret_cast<const float2*>(ap + 8 * GST);
            }
            float2 bv[8];
            #pragma unroll
            for (int jn = 0; jn < 8; jn++)
                bv[jn] = *reinterpret_cast<const float2*>(bBase + jn * 8 * GST + kb);
            #pragma unroll
            for (int im = 0; im < 4; im++)
                #pragma unroll
                for (int jn = 0; jn < 8; jn++)
                    mma_tf32(acc[im][jn],
                             av[im][0].x, av[im][1].x, av[im][0].y, av[im][1].y,
                             bv[jn].x, bv[jn].y);
        }
        __syncthreads();
    }

    // ---- epilogue: bias (+ q-scale / tf32 round for mode 0) ----
    #pragma unroll
    for (int im = 0; im < 4; im++) {
        #pragma unroll
        for (int jn = 0; jn < 8; jn++) {
            #pragma unroll
            for (int q = 0; q < 4; q++) {
                const int row = m0 + wm * 64 + im * 16 + g + ((q >= 2) ? 8 : 0);
                const int col = n0 + wn * 64 + jn * 8 + 2 * t + (q & 1);
                float v = acc[im][jn][q] + bias[col];
                if (mode == 0) {
                    if (col < CDIM) v *= SCALE_Q;
                    Cp[(size_t)row * ldc + col] = tf32r(v);
                } else {
                    Cp[(size_t)row * ldc + col] = v;
                }
            }
        }
    }
}

// ---------------------------------------------------------------------------
// Attention kernel: one CTA per (window, head). 128 threads (4 warps).
// smem: sU holds q|k (2 x 64x40) then is reused for P (64x72) after the
// score MMA; svT (32x72) holds V transposed. 29.75 KB total.
// ---------------------------------------------------------------------------
__global__ __launch_bounds__(128) void k_attn() {
    __shared__ float sU[5120];        // sq = sU[0..2560), sk = sU[2560..5120); later sS
    __shared__ float svT[32 * 72];

    float* sq = sU;
    float* sk = sU + 2560;
    float* sS = sU;                   // reused after score MMA

    const int b = blockIdx.x;
    const int h = blockIdx.y;
    const int tid  = threadIdx.x;
    const int lane = tid & 31;
    const int warp = tid >> 5;
    const int g = lane >> 2, t = lane & 3;

    const float* qb = g_qkv + (size_t)b * N_ACT * (3 * CDIM) + h * HD;
    const float* kb = qb + CDIM;
    const float* vb = qb + 2 * CDIM;

    // ---- load q, k (perm-8 layout, stride 40), v transposed (stride 72) ----
    for (int i = tid; i < 64 * 8; i += 128) {
        int r = i >> 3, c4 = i & 7, cb = c4 * 4;
        float4 vq, vk, vv;
        if (r < N_ACT) {
            vq = *reinterpret_cast<const float4*>(qb + (size_t)r * (3 * CDIM) + cb);
            vk = *reinterpret_cast<const float4*>(kb + (size_t)r * (3 * CDIM) + cb);
            vv = *reinterpret_cast<const float4*>(vb + (size_t)r * (3 * CDIM) + cb);
        } else {
            vq = vk = vv = make_float4(0.f, 0.f, 0.f, 0.f);
        }
        int base = r * 40 + (cb & 24) + ((cb >> 2) & 1);
        sq[base + 0] = vq.x; sq[base + 2] = vq.y; sq[base + 4] = vq.z; sq[base + 6] = vq.w;
        sk[base + 0] = vk.x; sk[base + 2] = vk.y; sk[base + 4] = vk.z; sk[base + 6] = vk.w;
        int pr = (r & 56) + (r & 3) * 2 + ((r >> 2) & 1);   // permuted token pos
        svT[(cb + 0) * 72 + pr] = vv.x;
        svT[(cb + 1) * 72 + pr] = vv.y;
        svT[(cb + 2) * 72 + pr] = vv.z;
        svT[(cb + 3) * 72 + pr] = vv.w;
    }
    __syncthreads();

    // ---- scores S = q @ k^T : warp handles rows 16*warp..+15 ----
    float sacc[8][4];
    #pragma unroll
    for (int jn = 0; jn < 8; jn++)
        #pragma unroll
        for (int q = 0; q < 4; q++) sacc[jn][q] = 0.f;

    #pragma unroll
    for (int ks = 0; ks < 4; ks++) {
        const int k0 = ks * 8 + 2 * t;
        const float* ap = sq + (16 * warp + g) * 40 + k0;
        float2 a0 = *reinterpret_cast<const float2*>(ap);
        float2 a1 = *reinterpret_cast<const float2*>(ap + 8 * 40);
        #pragma unroll
        for (int jn = 0; jn < 8; jn++) {
            float2 bp = *reinterpret_cast<const float2*>(sk + (jn * 8 + g) * 40 + k0);
            mma_tf32(sacc[jn], a0.x, a1.x, a0.y, a1.y, bp.x, bp.y);
        }
    }

    // ---- mask + register softmax (rows r0=16w+g, r1=r0+8) ----
    float mx[2] = {-1e30f, -1e30f};
    #pragma unroll
    for (int jn = 0; jn < 8; jn++)
        #pragma unroll
        for (int q = 0; q < 4; q++) {
            int col = jn * 8 + 2 * t + (q & 1);
            float v = sacc[jn][q] + (col >= N_ACT ? -1e9f : 0.f);
            sacc[jn][q] = v;
            mx[q >> 1] = fmaxf(mx[q >> 1], v);
        }
    #pragma unroll
    for (int o = 1; o < 4; o <<= 1) {
        mx[0] = fmaxf(mx[0], __shfl_xor_sync(0xffffffffu, mx[0], o));
        mx[1] = fmaxf(mx[1], __shfl_xor_sync(0xffffffffu, mx[1], o));
    }
    float sum[2] = {0.f, 0.f};
    #pragma unroll
    for (int jn = 0; jn < 8; jn++)
        #pragma unroll
        for (int q = 0; q < 4; q++) {
            float e = __expf(sacc[jn][q] - mx[q >> 1]);
            sacc[jn][q] = e;
            sum[q >> 1] += e;
        }
    #pragma unroll
    for (int o = 1; o < 4; o <<= 1) {
        sum[0] += __shfl_xor_sync(0xffffffffu, sum[0], o);
        sum[1] += __shfl_xor_sync(0xffffffffu, sum[1], o);
    }
    const float inv0 = 1.f / sum[0], inv1 = 1.f / sum[1];

    // all warps done reading sq/sk before sS overwrites the region
    __syncthreads();

    // store P (tf32) into sS with perm-8 k layout (own-warp rows only)
    #pragma unroll
    for (int jn = 0; jn < 8; jn++)
        #pragma unroll
        for (int q = 0; q < 4; q++) {
            int col = jn * 8 + 2 * t + (q & 1);
            int row = 16 * warp + g + ((q >= 2) ? 8 : 0);
            int pc = (col & 56) + (col & 3) * 2 + ((col >> 2) & 1);
            sS[row * 72 + pc] = tf32r(sacc[jn][q] * ((q >= 2) ? inv1 : inv0));
        }
    __syncwarp();

    // ---- O = P @ V : [16 x 32] per warp, K = 64 ----
    float oacc[4][4];
    #pragma unroll
    for (int jn = 0; jn < 4; jn++)
        #pragma unroll
        for (int q = 0; q < 4; q++) oacc[jn][q] = 0.f;

    #pragma unroll
    for (int ks = 0; ks < 8; ks++) {
        const int k0 = ks * 8 + 2 * t;
        const float* ap = sS + (16 * warp + g) * 72 + k0;
        float2 a0 = *reinterpret_cast<const float2*>(ap);
        float2 a1 = *reinterpret_cast<const float2*>(ap + 8 * 72);
        #pragma unroll
        for (int jn = 0; jn < 4; jn++) {
            float2 bp = *reinterpret_cast<const float2*>(svT + (jn * 8 + g) * 72 + k0);
            mma_tf32(oacc[jn], a0.x, a1.x, a0.y, a1.y, bp.x, bp.y);
        }
    }

    // ---- write O into q-slot of g_qkv (dead after load barrier) ----
    #pragma unroll
    for (int jn = 0; jn < 4; jn++)
        #pragma unroll
        for (int q = 0; q < 4; q++) {
            int row = 16 * warp + g + ((q >= 2) ? 8 : 0);
            int col = jn * 8 + 2 * t + (q & 1);
            if (row < N_ACT)
                g_qkv[((size_t)b * N_ACT + row) * (3 * CDIM) + h * HD + col] = oacc[jn][q];
        }
}

// ---------------------------------------------------------------------------
// Launch (static smem only; plain launches; graph-capturable)
// ---------------------------------------------------------------------------
extern "C" void kernel_launch(void* const* d_in, const int* in_sizes, int n_in,
                              void* d_out, int out_size) {
    const float *x = nullptr, *qkvw = nullptr, *qkvb = nullptr, *projw = nullptr, *projb = nullptr;
    for (int i = 0; i < n_in; i++) {
        int s = in_sizes[i];
        if (s == CDIM * 3 * CDIM)      qkvw = (const float*)d_in[i];
        else if (s == 3 * CDIM)        qkvb = (const float*)d_in[i];
        else if (s == CDIM * CDIM)     projw = (const float*)d_in[i];
        else if (s == CDIM)            projb = (const float*)d_in[i];
        else                           x = (const float*)d_in[i];
    }
    float* out = (float*)d_out;

    // weight pre-transpose + tf32 rounding
    ktranspose<<<dim3(3 * CDIM / 32, CDIM / 32), dim3(32, 32)>>>(qkvw, CDIM, 3 * CDIM, 0);
    ktranspose<<<dim3(CDIM / 32, CDIM / 32), dim3(32, 32)>>>(projw, CDIM, CDIM, 1);

    // QKV GEMM: g_qkv[122880 x 1536] = x @ qkv_w (+bias, q*scale, tf32)
    kgemm<<<dim3(3 * CDIM / 128, MROWS / 128), 128>>>(x, qkvb, projb, out, 0);

    // attention per (window, head); O overwrites q-slot of g_qkv
    k_attn<<<dim3(BWIN, NHEAD), 128>>>();

    // proj GEMM: out[122880 x 512] = O @ proj_w + bias
    kgemm<<<dim3(CDIM / 128, MROWS / 128), 128>>>(x, qkvb, projb, out, 1);
}